// round 14
// baseline (speedup 1.0000x reference)
#include <cuda_runtime.h>
#include <cuda_bf16.h>
#include <cstdint>
#include <cstddef>

#define NB   16
#define NSQ  1024
#define NSK  1024
#define NHD  8
#define HD   32
#define HDIM 256
#define L2E    1.4426950408889634f
#define QSCALE (1.4426950408889634f / 5.656854249492380f)   // log2(e)/sqrt(32)
#define SMEM_ATTN 66048                         // buf[16][1032] floats
#define SMEM_PROJ ((2*128*36 + 2*64*36) * 4)    // As[2][128][36] + Ws[2][64][36] = 55296 B

// ---------------- device scratch (allocation-free) ----------------
__device__ float g_Q [NB*NHD*NSQ*HD];   // pre-scaled by QSCALE, tf32-rounded
__device__ float g_K [NB*NHD*NSK*HD];   // tf32-rounded, [b,h,s,d] layout
__device__ float g_cs[NB*NHD*NSK];      // attention column sums
__device__ float g_res[NB*HDIM];        // sum_s q
__device__ float g_t  [NB*NHD*HDIM];    // colsum . v

// ---------------- helpers ----------------
__device__ __forceinline__ float tf32r(float x){
    unsigned u; asm("cvt.rna.tf32.f32 %0, %1;" : "=r"(u) : "f"(x)); return __uint_as_float(u);
}
__device__ __forceinline__ float ex2f_(float x){
    float y; asm("ex2.approx.ftz.f32 %0, %1;" : "=f"(y) : "f"(x)); return y;
}
__device__ __forceinline__ void mma_tf32(float* c, const float* a, const float* b){
    asm volatile(
        "mma.sync.aligned.m16n8k8.row.col.f32.tf32.tf32.f32 "
        "{%0,%1,%2,%3}, {%4,%5,%6,%7}, {%8,%9}, {%0,%1,%2,%3};\n"
        : "+f"(c[0]), "+f"(c[1]), "+f"(c[2]), "+f"(c[3])
        : "r"(__float_as_uint(a[0])), "r"(__float_as_uint(a[1])),
          "r"(__float_as_uint(a[2])), "r"(__float_as_uint(a[3])),
          "r"(__float_as_uint(b[0])), "r"(__float_as_uint(b[1])));
}

// ---------------- Q/K projection GEMM (tf32 mma): C[m,n] = A[m,:].W[n,:] ----------------
// grid (4, 128, 2), block 256. CTA tile 128x64, warp tile 32x32.
// Double-buffered smem mainloop, float4 STS staging, smem-staged coalesced epilogue.
__global__ __launch_bounds__(256, 2) void proj_kernel(
    const float* __restrict__ qin, const float* __restrict__ kin,
    const float* __restrict__ WQ,  const float* __restrict__ WK)
{
    extern __shared__ float psm[];
    float (*As)[128][36] = reinterpret_cast<float(*)[128][36]>(psm);
    float (*Ws)[64][36]  = reinterpret_cast<float(*)[64][36]>(psm + 2 * 128 * 36);

    const int z = blockIdx.z;
    const float* A = z ? kin : qin;
    const float* W = z ? WK  : WQ;
    const int n0 = blockIdx.x * 64, m0 = blockIdx.y * 128;
    const int t = threadIdx.x, w = t >> 5, lane = t & 31, g = lane >> 2, tig = lane & 3;
    const int mw = (w >> 1) * 32, nw = (w & 1) * 32;

    int rA[4], cA[4], rW[2], cW[2];
    #pragma unroll
    for (int i = 0; i < 4; i++){ int f = i * 256 + t; rA[i] = f >> 3; cA[i] = (f & 7) * 4; }
    #pragma unroll
    for (int i = 0; i < 2; i++){ int f = i * 256 + t; rW[i] = f >> 3; cW[i] = (f & 7) * 4; }

    float acc[2][4][4];
    #pragma unroll
    for (int mt = 0; mt < 2; mt++)
        #pragma unroll
        for (int nt = 0; nt < 4; nt++)
            #pragma unroll
            for (int r = 0; r < 4; r++) acc[mt][nt][r] = 0.f;

    float4 pa[4], pw[2];
    #pragma unroll
    for (int i = 0; i < 4; i++)
        pa[i] = *reinterpret_cast<const float4*>(A + (size_t)(m0 + rA[i]) * HDIM + cA[i]);
    #pragma unroll
    for (int i = 0; i < 2; i++)
        pw[i] = *reinterpret_cast<const float4*>(W + (size_t)(n0 + rW[i]) * HDIM + cW[i]);

    #pragma unroll
    for (int i = 0; i < 4; i++)
        *reinterpret_cast<float4*>(&As[0][rA[i]][cA[i]]) =
            make_float4(tf32r(pa[i].x), tf32r(pa[i].y), tf32r(pa[i].z), tf32r(pa[i].w));
    #pragma unroll
    for (int i = 0; i < 2; i++)
        *reinterpret_cast<float4*>(&Ws[0][rW[i]][cW[i]]) =
            make_float4(tf32r(pw[i].x), tf32r(pw[i].y), tf32r(pw[i].z), tf32r(pw[i].w));
    __syncthreads();

    for (int kc = 0; kc < 8; kc++){
        const int cur = kc & 1, nxt = cur ^ 1;
        if (kc < 7){
            #pragma unroll
            for (int i = 0; i < 4; i++)
                pa[i] = *reinterpret_cast<const float4*>(A + (size_t)(m0 + rA[i]) * HDIM + (kc + 1) * 32 + cA[i]);
            #pragma unroll
            for (int i = 0; i < 2; i++)
                pw[i] = *reinterpret_cast<const float4*>(W + (size_t)(n0 + rW[i]) * HDIM + (kc + 1) * 32 + cW[i]);
        }
        #pragma unroll
        for (int ks = 0; ks < 4; ks++){
            float a[2][4], bb[4][2];
            #pragma unroll
            for (int mt = 0; mt < 2; mt++){
                int r = mw + mt * 16;
                a[mt][0] = As[cur][r + g    ][ks * 8 + tig];
                a[mt][1] = As[cur][r + g + 8][ks * 8 + tig];
                a[mt][2] = As[cur][r + g    ][ks * 8 + tig + 4];
                a[mt][3] = As[cur][r + g + 8][ks * 8 + tig + 4];
            }
            #pragma unroll
            for (int nt = 0; nt < 4; nt++){
                int n = nw + nt * 8 + g;
                bb[nt][0] = Ws[cur][n][ks * 8 + tig];
                bb[nt][1] = Ws[cur][n][ks * 8 + tig + 4];
            }
            #pragma unroll
            for (int mt = 0; mt < 2; mt++)
                #pragma unroll
                for (int nt = 0; nt < 4; nt++)
                    mma_tf32(acc[mt][nt], a[mt], bb[nt]);
        }
        if (kc < 7){
            #pragma unroll
            for (int i = 0; i < 4; i++)
                *reinterpret_cast<float4*>(&As[nxt][rA[i]][cA[i]]) =
                    make_float4(tf32r(pa[i].x), tf32r(pa[i].y), tf32r(pa[i].z), tf32r(pa[i].w));
            #pragma unroll
            for (int i = 0; i < 2; i++)
                *reinterpret_cast<float4*>(&Ws[nxt][rW[i]][cW[i]]) =
                    make_float4(tf32r(pw[i].x), tf32r(pw[i].y), tf32r(pw[i].z), tf32r(pw[i].w));
        }
        __syncthreads();
    }

    // ---- epilogue: stage C through smem, write fully coalesced ----
    float (*Cs)[68] = reinterpret_cast<float(*)[68]>(psm);   // 128 x 68 floats
    __syncthreads();
    #pragma unroll
    for (int mt = 0; mt < 2; mt++)
        #pragma unroll
        for (int nt = 0; nt < 4; nt++){
            int col = nw + nt * 8 + 2 * tig;
            #pragma unroll
            for (int rh = 0; rh < 2; rh++){
                int row = mw + mt * 16 + g + rh * 8;
                Cs[row][col    ] = acc[mt][nt][rh * 2 + 0];
                Cs[row][col + 1] = acc[mt][nt][rh * 2 + 1];
            }
        }
    __syncthreads();

    const int bq = m0 >> 10;
    const int s0 = m0 & 1023;
    #pragma unroll
    for (int i = 0; i < 8; i++){
        int f = i * 256 + t;
        int row = f >> 4, c4 = (f & 15) * 4;
        int nglob = n0 + c4;
        int hh = nglob >> 5, d0 = nglob & 31;
        float4 v = *reinterpret_cast<const float4*>(&Cs[row][c4]);
        size_t o = (((size_t)bq * NHD + hh) * 1024 + (s0 + row)) * HD + d0;
        if (z == 0){
            *reinterpret_cast<float4*>(g_Q + o) =
                make_float4(tf32r(v.x * QSCALE), tf32r(v.y * QSCALE),
                            tf32r(v.z * QSCALE), tf32r(v.w * QSCALE));
        } else {
            *reinterpret_cast<float4*>(g_K + o) =
                make_float4(tf32r(v.x), tf32r(v.y), tf32r(v.z), tf32r(v.w));
        }
    }
}

// ---------------- zero accumulators ----------------
__global__ void zero_kernel(){
    int i = blockIdx.x * 256 + threadIdx.x;
    g_cs[i] = 0.f;
    if (i < NB * HDIM)       g_res[i] = 0.f;
    if (i < NB * NHD * HDIM) g_t[i]   = 0.f;
}

// ---------------- res += partial sums of q over s ----------------
__global__ __launch_bounds__(256) void res_kernel(const float* __restrict__ qin){
    int b = blockIdx.x, c = blockIdx.y, j = threadIdx.x;
    const float* p = qin + ((size_t)b * NSQ + c * 64) * HDIM + j;
    float s = 0.f;
    #pragma unroll 8
    for (int i = 0; i < 64; i++) s += p[(size_t)i * HDIM];
    atomicAdd(&g_res[b * HDIM + j], s);
}

// ---------------- fused attention: QK^T + bias + softmax + write + colsum ----------------
// grid (16, 8, 64), block 512, 2 CTAs/SM. (Best measured configuration — unchanged.)
__global__ __launch_bounds__(512, 2) void attn_kernel(const float* __restrict__ bias,
                                                      float* __restrict__ attn)
{
    extern __shared__ char sm[];
    float (*buf)[1032] = reinterpret_cast<float(*)[1032]>(sm);
    __shared__ float partial[16][17];
    __shared__ float invb[16];

    const int t = threadIdx.x, wv = t >> 5, lane = t & 31, g = lane >> 2, tig = lane & 3;
    const int b = blockIdx.x, h = blockIdx.y, qb = blockIdx.z * 16;

    const float* Qp = g_Q + ((size_t)(b * NHD + h)) * NSQ * HD;
    const float* Kp = g_K + ((size_t)(b * NHD + h)) * NSK * HD;
    const float* bp = bias + ((size_t)h * NSQ + qb) * NSK;
    float*       ap = attn + (((size_t)(b * NHD + h)) * NSQ + qb) * NSK;

    #pragma unroll
    for (int i = 0; i < 8; i++){
        int f = i * 512 + t;
        int row = f >> 8, c4 = (f & 255) * 4;
        *reinterpret_cast<float4*>(&buf[row][c4]) =
            *reinterpret_cast<const float4*>(bp + (size_t)row * NSK + c4);
    }

    float4 q0a = *reinterpret_cast<const float4*>(Qp + (size_t)(qb + g    ) * HD +      4 * tig);
    float4 q0b = *reinterpret_cast<const float4*>(Qp + (size_t)(qb + g    ) * HD + 16 + 4 * tig);
    float4 q1a = *reinterpret_cast<const float4*>(Qp + (size_t)(qb + g + 8) * HD +      4 * tig);
    float4 q1b = *reinterpret_cast<const float4*>(Qp + (size_t)(qb + g + 8) * HD + 16 + 4 * tig);

    const int n = wv * 8 + g;
    const float* krow = Kp + (size_t)n * HD;

    float4 kc0 = *reinterpret_cast<const float4*>(krow +      4 * tig);
    float4 kc1 = *reinterpret_cast<const float4*>(krow + 16 + 4 * tig);

    __syncthreads();

    float srow0 = 0.f, srow1 = 0.f;

    #pragma unroll 2
    for (int kt = 0; kt < 8; kt++){
        const int col0 = kt * 128 + wv * 8 + 2 * tig;
        float2 bv0 = *reinterpret_cast<const float2*>(&buf[g    ][col0]);
        float2 bv1 = *reinterpret_cast<const float2*>(&buf[g + 8][col0]);

        float4 kn0, kn1;
        if (kt < 7){
            kn0 = *reinterpret_cast<const float4*>(krow + (size_t)(kt + 1) * 128 * HD +      4 * tig);
            kn1 = *reinterpret_cast<const float4*>(krow + (size_t)(kt + 1) * 128 * HD + 16 + 4 * tig);
        }

        float accA[4] = {0.f, 0.f, 0.f, 0.f};
        float accB[4] = {0.f, 0.f, 0.f, 0.f};
        const float* k0 = &kc0.x;
        const float* k1 = &kc1.x;
        const float* p0a = &q0a.x; const float* p0b = &q0b.x;
        const float* p1a = &q1a.x; const float* p1b = &q1b.x;
        #pragma unroll
        for (int s = 0; s < 2; s++){
            float aA[4] = { p0a[s], p1a[s], p0b[s], p1b[s] };
            float bA[2] = { k0[s], k1[s] };
            mma_tf32(accA, aA, bA);
            float aB[4] = { p0a[s + 2], p1a[s + 2], p0b[s + 2], p1b[s + 2] };
            float bB[2] = { k0[s + 2], k1[s + 2] };
            mma_tf32(accB, aB, bB);
        }

        float e0 = ex2f_(fmaf(bv0.x, L2E, accA[0] + accB[0]));
        float e1 = ex2f_(fmaf(bv0.y, L2E, accA[1] + accB[1]));
        float e2 = ex2f_(fmaf(bv1.x, L2E, accA[2] + accB[2]));
        float e3 = ex2f_(fmaf(bv1.y, L2E, accA[3] + accB[3]));
        *reinterpret_cast<float2*>(&buf[g    ][col0]) = make_float2(e0, e1);
        *reinterpret_cast<float2*>(&buf[g + 8][col0]) = make_float2(e2, e3);
        srow0 += e0 + e1;
        srow1 += e2 + e3;

        kc0 = kn0; kc1 = kn1;
    }

    srow0 += __shfl_xor_sync(0xffffffffu, srow0, 1);
    srow0 += __shfl_xor_sync(0xffffffffu, srow0, 2);
    srow1 += __shfl_xor_sync(0xffffffffu, srow1, 1);
    srow1 += __shfl_xor_sync(0xffffffffu, srow1, 2);
    if (tig == 0){
        partial[g    ][wv] = srow0;
        partial[g + 8][wv] = srow1;
    }
    __syncthreads();
    if (t < 256){
        float s = partial[t >> 4][t & 15];
        s += __shfl_down_sync(0xffffffffu, s, 8, 16);
        s += __shfl_down_sync(0xffffffffu, s, 4, 16);
        s += __shfl_down_sync(0xffffffffu, s, 2, 16);
        s += __shfl_down_sync(0xffffffffu, s, 1, 16);
        if ((t & 15) == 0) invb[t >> 4] = 1.0f / s;
    }
    __syncthreads();

    const int c0 = 2 * t;
    float csx = 0.f, csy = 0.f;
    #pragma unroll 4
    for (int row = 0; row < 16; row++){
        float inv = invb[row];
        float2 v = *reinterpret_cast<const float2*>(&buf[row][c0]);
        v.x *= inv; v.y *= inv;
        *reinterpret_cast<float2*>(ap + (size_t)row * NSK + c0) = v;
        csx += v.x; csy += v.y;
    }
    float* csp = g_cs + (size_t)(b * NHD + h) * NSK + c0;
    atomicAdd(csp + 0, csx);
    atomicAdd(csp + 1, csy);
}

// ---------------- t[b,h,j] += sum_{k in chunk} colsum[b,h,k] * v[b,k,j] ----------------
__global__ __launch_bounds__(256) void tred_kernel(const float* __restrict__ v){
    __shared__ float cs[NHD][64];
    int b = blockIdx.x, c = blockIdx.y, t = threadIdx.x;
    for (int i = t; i < NHD * 64; i += 256){
        int hh = i >> 6, kk = i & 63;
        cs[hh][kk] = g_cs[(size_t)(b * NHD + hh) * NSK + c * 64 + kk];
    }
    __syncthreads();
    float acc[NHD];
    #pragma unroll
    for (int hh = 0; hh < NHD; hh++) acc[hh] = 0.f;
    const float* vp = v + ((size_t)b * NSK + c * 64) * HDIM + t;
    #pragma unroll 4
    for (int k = 0; k < 64; k++){
        float vv = vp[(size_t)k * HDIM];
        #pragma unroll
        for (int hh = 0; hh < NHD; hh++) acc[hh] += cs[hh][k] * vv;
    }
    #pragma unroll
    for (int hh = 0; hh < NHD; hh++)
        atomicAdd(&g_t[(b * NHD + hh) * HDIM + t], acc[hh]);
}

// ---------------- xs = t @ W_V^T (per head), MLP + BN(eval) + mish + residual ----------------
__global__ __launch_bounds__(256) void final_kernel(
    const float* __restrict__ WV, const float* __restrict__ W1, const float* __restrict__ b1,
    const float* __restrict__ gamma, const float* __restrict__ beta,
    const float* __restrict__ rm, const float* __restrict__ rv, float* __restrict__ out)
{
    __shared__ float sxs[HDIM];
    int b = blockIdx.x, n = threadIdx.x;
    const float* tp = g_t + (b * NHD + (n >> 5)) * HDIM;
    const float* wv = WV + (size_t)n * HDIM;
    float s = 0.f;
    #pragma unroll 8
    for (int j = 0; j < HDIM; j++) s += tp[j] * wv[j];
    sxs[n] = s;
    __syncthreads();
    const float* w1 = W1 + (size_t)n * HDIM;
    float hsum = b1[n];
    #pragma unroll 8
    for (int j = 0; j < HDIM; j++) hsum += sxs[j] * w1[j];
    float hn = (hsum - rm[n]) * rsqrtf(rv[n] + 1e-5f) * gamma[n] + beta[n];
    float sp = log1pf(expf(hn));
    out[b * HDIM + n] = hn * tanhf(sp) + g_res[b * HDIM + n];
}

// ---------------- launch ----------------
extern "C" void kernel_launch(void* const* d_in, const int* in_sizes, int n_in,
                              void* d_out, int out_size)
{
    const float* q    = (const float*)d_in[0];
    const float* k    = (const float*)d_in[1];
    const float* v    = (const float*)d_in[2];
    const float* bias = (const float*)d_in[3];
    const float* WQ   = (const float*)d_in[4];
    const float* WK   = (const float*)d_in[5];
    const float* WV   = (const float*)d_in[6];
    const float* W1   = (const float*)d_in[7];
    const float* b1   = (const float*)d_in[8];
    const float* gm   = (const float*)d_in[9];
    const float* bt   = (const float*)d_in[10];
    const float* rm   = (const float*)d_in[11];
    const float* rv   = (const float*)d_in[12];

    float* out  = (float*)d_out;
    float* attn = out + NB * HDIM;   // (out, attention) in tuple order

    cudaFuncSetAttribute(attn_kernel, cudaFuncAttributeMaxDynamicSharedMemorySize, SMEM_ATTN);
    cudaFuncSetAttribute(proj_kernel, cudaFuncAttributeMaxDynamicSharedMemorySize, SMEM_PROJ);

    zero_kernel<<<512, 256>>>();
    // MEASUREMENT: proj launched twice (second writes identical data).
    // Delta vs R13's 366.2us total == proj's true in-stream duration.
    proj_kernel<<<dim3(4, 128, 2), 256, SMEM_PROJ>>>(q, k, WQ, WK);
    proj_kernel<<<dim3(4, 128, 2), 256, SMEM_PROJ>>>(q, k, WQ, WK);
    res_kernel<<<dim3(NB, 16), 256>>>(q);
    attn_kernel<<<dim3(NB, NHD, 64), 512, SMEM_ATTN>>>(bias, attn);
    tred_kernel<<<dim3(NB, 16), 256>>>(v);
    final_kernel<<<NB, 256>>>(WV, W1, b1, gm, bt, rm, rv, out);
}

// round 15
// speedup vs baseline: 1.8910x; 1.8910x over previous
#include <cuda_runtime.h>
#include <cuda_bf16.h>
#include <cstdint>
#include <cstddef>

#define NB   16
#define NSQ  1024
#define NSK  1024
#define NHD  8
#define HD   32
#define HDIM 256
#define L2E    1.4426950408889634f
#define QSCALE (1.4426950408889634f / 5.656854249492380f)   // log2(e)/sqrt(32)
#define SMEM_ATTN 66048                         // buf[16][1032] floats
#define SMEM_PROJ ((2*128*36 + 2*64*36) * 4)    // As[2][128][36] + Ws[2][64][36] = 55296 B

// ---------------- device scratch (allocation-free) ----------------
// Q/K stored as bf16 in k-PERMUTED layout, 64 B per row of 32 head-dims:
//   byte(d) = (d>>4)*32 + ((d&7)>>1)*8 + ((d>>3)&1)*4 + (d&1)*2
// so thread tig's m16n8k16 fragment pairs {2t,2t+1} and {8+2t,9+2t} of each
// 16-wide chunk are one contiguous uint2 at chunk*32 + 8*tig.
__device__ __nv_bfloat16 g_Qh[NB*NHD*NSQ*HD];   // pre-scaled by QSCALE
__device__ __nv_bfloat16 g_Kh[NB*NHD*NSK*HD];
__device__ float g_cs[NB*NHD*NSK];      // attention column sums
__device__ float g_res[NB*HDIM];        // sum_s q
__device__ float g_t  [NB*NHD*HDIM];    // colsum . v

// ---------------- helpers ----------------
__device__ __forceinline__ float tf32r(float x){
    unsigned u; asm("cvt.rna.tf32.f32 %0, %1;" : "=r"(u) : "f"(x)); return __uint_as_float(u);
}
__device__ __forceinline__ float ex2f_(float x){
    float y; asm("ex2.approx.ftz.f32 %0, %1;" : "=f"(y) : "f"(x)); return y;
}
__device__ __forceinline__ unsigned pbf(float lo, float hi){
    unsigned d; asm("cvt.rn.bf16x2.f32 %0, %1, %2;" : "=r"(d) : "f"(hi), "f"(lo)); return d;
}
__device__ __forceinline__ void mma_tf32(float* c, const float* a, const float* b){
    asm volatile(
        "mma.sync.aligned.m16n8k8.row.col.f32.tf32.tf32.f32 "
        "{%0,%1,%2,%3}, {%4,%5,%6,%7}, {%8,%9}, {%0,%1,%2,%3};\n"
        : "+f"(c[0]), "+f"(c[1]), "+f"(c[2]), "+f"(c[3])
        : "r"(__float_as_uint(a[0])), "r"(__float_as_uint(a[1])),
          "r"(__float_as_uint(a[2])), "r"(__float_as_uint(a[3])),
          "r"(__float_as_uint(b[0])), "r"(__float_as_uint(b[1])));
}
__device__ __forceinline__ void mma_bf16(float* c, unsigned a0, unsigned a1, unsigned a2,
                                         unsigned a3, unsigned b0, unsigned b1){
    asm volatile(
        "mma.sync.aligned.m16n8k16.row.col.f32.bf16.bf16.f32 "
        "{%0,%1,%2,%3}, {%4,%5,%6,%7}, {%8,%9}, {%0,%1,%2,%3};\n"
        : "+f"(c[0]), "+f"(c[1]), "+f"(c[2]), "+f"(c[3])
        : "r"(a0), "r"(a1), "r"(a2), "r"(a3), "r"(b0), "r"(b1));
}

// ---------------- Q/K projection GEMM (tf32 mma): C[m,n] = A[m,:].W[n,:] ----------------
// grid (4, 128, 2), block 256. CTA tile 128x64. Epilogue packs bf16 permuted rows.
__global__ __launch_bounds__(256, 2) void proj_kernel(
    const float* __restrict__ qin, const float* __restrict__ kin,
    const float* __restrict__ WQ,  const float* __restrict__ WK)
{
    extern __shared__ float psm[];
    float (*As)[128][36] = reinterpret_cast<float(*)[128][36]>(psm);
    float (*Ws)[64][36]  = reinterpret_cast<float(*)[64][36]>(psm + 2 * 128 * 36);

    const int z = blockIdx.z;
    const float* A = z ? kin : qin;
    const float* W = z ? WK  : WQ;
    const int n0 = blockIdx.x * 64, m0 = blockIdx.y * 128;
    const int t = threadIdx.x, w = t >> 5, lane = t & 31, g = lane >> 2, tig = lane & 3;
    const int mw = (w >> 1) * 32, nw = (w & 1) * 32;

    int rA[4], cA[4], rW[2], cW[2];
    #pragma unroll
    for (int i = 0; i < 4; i++){ int f = i * 256 + t; rA[i] = f >> 3; cA[i] = (f & 7) * 4; }
    #pragma unroll
    for (int i = 0; i < 2; i++){ int f = i * 256 + t; rW[i] = f >> 3; cW[i] = (f & 7) * 4; }

    float acc[2][4][4];
    #pragma unroll
    for (int mt = 0; mt < 2; mt++)
        #pragma unroll
        for (int nt = 0; nt < 4; nt++)
            #pragma unroll
            for (int r = 0; r < 4; r++) acc[mt][nt][r] = 0.f;

    float4 pa[4], pw[2];
    #pragma unroll
    for (int i = 0; i < 4; i++)
        pa[i] = *reinterpret_cast<const float4*>(A + (size_t)(m0 + rA[i]) * HDIM + cA[i]);
    #pragma unroll
    for (int i = 0; i < 2; i++)
        pw[i] = *reinterpret_cast<const float4*>(W + (size_t)(n0 + rW[i]) * HDIM + cW[i]);

    #pragma unroll
    for (int i = 0; i < 4; i++)
        *reinterpret_cast<float4*>(&As[0][rA[i]][cA[i]]) =
            make_float4(tf32r(pa[i].x), tf32r(pa[i].y), tf32r(pa[i].z), tf32r(pa[i].w));
    #pragma unroll
    for (int i = 0; i < 2; i++)
        *reinterpret_cast<float4*>(&Ws[0][rW[i]][cW[i]]) =
            make_float4(tf32r(pw[i].x), tf32r(pw[i].y), tf32r(pw[i].z), tf32r(pw[i].w));
    __syncthreads();

    for (int kc = 0; kc < 8; kc++){
        const int cur = kc & 1, nxt = cur ^ 1;
        if (kc < 7){
            #pragma unroll
            for (int i = 0; i < 4; i++)
                pa[i] = *reinterpret_cast<const float4*>(A + (size_t)(m0 + rA[i]) * HDIM + (kc + 1) * 32 + cA[i]);
            #pragma unroll
            for (int i = 0; i < 2; i++)
                pw[i] = *reinterpret_cast<const float4*>(W + (size_t)(n0 + rW[i]) * HDIM + (kc + 1) * 32 + cW[i]);
        }
        #pragma unroll
        for (int ks = 0; ks < 4; ks++){
            float a[2][4], bb[4][2];
            #pragma unroll
            for (int mt = 0; mt < 2; mt++){
                int r = mw + mt * 16;
                a[mt][0] = As[cur][r + g    ][ks * 8 + tig];
                a[mt][1] = As[cur][r + g + 8][ks * 8 + tig];
                a[mt][2] = As[cur][r + g    ][ks * 8 + tig + 4];
                a[mt][3] = As[cur][r + g + 8][ks * 8 + tig + 4];
            }
            #pragma unroll
            for (int nt = 0; nt < 4; nt++){
                int n = nw + nt * 8 + g;
                bb[nt][0] = Ws[cur][n][ks * 8 + tig];
                bb[nt][1] = Ws[cur][n][ks * 8 + tig + 4];
            }
            #pragma unroll
            for (int mt = 0; mt < 2; mt++)
                #pragma unroll
                for (int nt = 0; nt < 4; nt++)
                    mma_tf32(acc[mt][nt], a[mt], bb[nt]);
        }
        if (kc < 7){
            #pragma unroll
            for (int i = 0; i < 4; i++)
                *reinterpret_cast<float4*>(&As[nxt][rA[i]][cA[i]]) =
                    make_float4(tf32r(pa[i].x), tf32r(pa[i].y), tf32r(pa[i].z), tf32r(pa[i].w));
            #pragma unroll
            for (int i = 0; i < 2; i++)
                *reinterpret_cast<float4*>(&Ws[nxt][rW[i]][cW[i]]) =
                    make_float4(tf32r(pw[i].x), tf32r(pw[i].y), tf32r(pw[i].z), tf32r(pw[i].w));
        }
        __syncthreads();
    }

    // ---- epilogue: stage C through smem, pack bf16 permuted rows, coalesced ----
    float (*Cs)[68] = reinterpret_cast<float(*)[68]>(psm);   // 128 x 68 floats
    __syncthreads();
    #pragma unroll
    for (int mt = 0; mt < 2; mt++)
        #pragma unroll
        for (int nt = 0; nt < 4; nt++){
            int col = nw + nt * 8 + 2 * tig;
            #pragma unroll
            for (int rh = 0; rh < 2; rh++){
                int row = mw + mt * 16 + g + rh * 8;
                Cs[row][col    ] = acc[mt][nt][rh * 2 + 0];
                Cs[row][col + 1] = acc[mt][nt][rh * 2 + 1];
            }
        }
    __syncthreads();

    const int bq = m0 >> 10;
    const int s0 = m0 & 1023;
    const float sc = (z == 0) ? QSCALE : 1.0f;
    char* outb = (z == 0) ? (char*)g_Qh : (char*)g_Kh;
    #pragma unroll
    for (int i = 0; i < 2; i++){
        int item = i * 256 + t;                 // 512 items: hh(2) x row(128) x chunk(2)
        int hhl = item >> 8, row = (item & 255) >> 1, chunk = item & 1;
        int colbase = hhl * 32 + chunk * 16;
        unsigned u[8];
        #pragma unroll
        for (int tt = 0; tt < 4; tt++){
            float d0 = Cs[row][colbase + 2*tt    ] * sc;
            float d1 = Cs[row][colbase + 2*tt + 1] * sc;
            float d8 = Cs[row][colbase + 8 + 2*tt    ] * sc;
            float d9 = Cs[row][colbase + 8 + 2*tt + 1] * sc;
            u[tt*2    ] = pbf(d0, d1);
            u[tt*2 + 1] = pbf(d8, d9);
        }
        int hh = (n0 >> 5) + hhl;
        size_t o = (((size_t)bq * NHD + hh) * 1024 + (s0 + row)) * 64 + chunk * 32;
        *reinterpret_cast<uint4*>(outb + o     ) = make_uint4(u[0], u[1], u[2], u[3]);
        *reinterpret_cast<uint4*>(outb + o + 16) = make_uint4(u[4], u[5], u[6], u[7]);
    }
}

// ---------------- zero accumulators ----------------
__global__ void zero_kernel(){
    int i = blockIdx.x * 256 + threadIdx.x;
    g_cs[i] = 0.f;
    if (i < NB * HDIM)       g_res[i] = 0.f;
    if (i < NB * NHD * HDIM) g_t[i]   = 0.f;
}

// ---------------- res += partial sums of q over s ----------------
__global__ __launch_bounds__(256) void res_kernel(const float* __restrict__ qin){
    int b = blockIdx.x, c = blockIdx.y, j = threadIdx.x;
    const float* p = qin + ((size_t)b * NSQ + c * 64) * HDIM + j;
    float s = 0.f;
    #pragma unroll 8
    for (int i = 0; i < 64; i++) s += p[(size_t)i * HDIM];
    atomicAdd(&g_res[b * HDIM + j], s);
}

// ---------------- fused attention: bf16 QK^T + bias + softmax + write + colsum ----------------
// grid (16, 8, 64), block 512, 2 CTAs/SM. m16n8k16 bf16, dual chains (k chunks),
// no in-loop barriers.
__global__ __launch_bounds__(512, 2) void attn_kernel(const float* __restrict__ bias,
                                                      float* __restrict__ attn)
{
    extern __shared__ char sm[];
    float (*buf)[1032] = reinterpret_cast<float(*)[1032]>(sm);
    __shared__ float partial[16][17];
    __shared__ float invb[16];

    const int t = threadIdx.x, wv = t >> 5, lane = t & 31, g = lane >> 2, tig = lane & 3;
    const int b = blockIdx.x, h = blockIdx.y, qb = blockIdx.z * 16;

    const char* Qb = (const char*)g_Qh + (((size_t)(b * NHD + h)) * 1024 + qb) * 64;
    const char* Kb = (const char*)g_Kh + ((size_t)(b * NHD + h)) * 1024 * 64;
    const float* bp = bias + ((size_t)h * NSQ + qb) * NSK;
    float*       ap = attn + (((size_t)(b * NHD + h)) * NSQ + qb) * NSK;

    // stage bias tile coalesced (16 rows x 1024 cols, float4)
    #pragma unroll
    for (int i = 0; i < 8; i++){
        int f = i * 512 + t;
        int row = f >> 8, c4 = (f & 255) * 4;
        *reinterpret_cast<float4*>(&buf[row][c4]) =
            *reinterpret_cast<const float4*>(bp + (size_t)row * NSK + c4);
    }

    // Q fragments (bf16 permuted rows, 64 B each): rows qb+g and qb+g+8
    uint2 qg0 = *reinterpret_cast<const uint2*>(Qb + (size_t)g * 64 +      8 * tig);
    uint2 qg1 = *reinterpret_cast<const uint2*>(Qb + (size_t)g * 64 + 32 + 8 * tig);
    uint2 qh0 = *reinterpret_cast<const uint2*>(Qb + (size_t)(g + 8) * 64 +      8 * tig);
    uint2 qh1 = *reinterpret_cast<const uint2*>(Qb + (size_t)(g + 8) * 64 + 32 + 8 * tig);

    const int n = wv * 8 + g;                 // this thread's K row within each 128-tile
    const char* krow = Kb + (size_t)n * 64;

    uint2 kc0 = *reinterpret_cast<const uint2*>(krow +      8 * tig);
    uint2 kc1 = *reinterpret_cast<const uint2*>(krow + 32 + 8 * tig);

    __syncthreads();   // bias staged

    float srow0 = 0.f, srow1 = 0.f;

    #pragma unroll 2
    for (int kt = 0; kt < 8; kt++){
        const int col0 = kt * 128 + wv * 8 + 2 * tig;
        float2 bv0 = *reinterpret_cast<const float2*>(&buf[g    ][col0]);
        float2 bv1 = *reinterpret_cast<const float2*>(&buf[g + 8][col0]);

        uint2 kn0, kn1;
        if (kt < 7){
            kn0 = *reinterpret_cast<const uint2*>(krow + (size_t)(kt + 1) * 8192 +      8 * tig);
            kn1 = *reinterpret_cast<const uint2*>(krow + (size_t)(kt + 1) * 8192 + 32 + 8 * tig);
        }

        float accA[4] = {0.f, 0.f, 0.f, 0.f};
        float accB[4] = {0.f, 0.f, 0.f, 0.f};
        mma_bf16(accA, qg0.x, qh0.x, qg0.y, qh0.y, kc0.x, kc0.y);   // k 0..15
        mma_bf16(accB, qg1.x, qh1.x, qg1.y, qh1.y, kc1.x, kc1.y);   // k 16..31

        float e0 = ex2f_(fmaf(bv0.x, L2E, accA[0] + accB[0]));
        float e1 = ex2f_(fmaf(bv0.y, L2E, accA[1] + accB[1]));
        float e2 = ex2f_(fmaf(bv1.x, L2E, accA[2] + accB[2]));
        float e3 = ex2f_(fmaf(bv1.y, L2E, accA[3] + accB[3]));
        *reinterpret_cast<float2*>(&buf[g    ][col0]) = make_float2(e0, e1);
        *reinterpret_cast<float2*>(&buf[g + 8][col0]) = make_float2(e2, e3);
        srow0 += e0 + e1;
        srow1 += e2 + e3;

        kc0 = kn0; kc1 = kn1;
    }

    srow0 += __shfl_xor_sync(0xffffffffu, srow0, 1);
    srow0 += __shfl_xor_sync(0xffffffffu, srow0, 2);
    srow1 += __shfl_xor_sync(0xffffffffu, srow1, 1);
    srow1 += __shfl_xor_sync(0xffffffffu, srow1, 2);
    if (tig == 0){
        partial[g    ][wv] = srow0;
        partial[g + 8][wv] = srow1;
    }
    __syncthreads();
    if (t < 256){
        float s = partial[t >> 4][t & 15];
        s += __shfl_down_sync(0xffffffffu, s, 8, 16);
        s += __shfl_down_sync(0xffffffffu, s, 4, 16);
        s += __shfl_down_sync(0xffffffffu, s, 2, 16);
        s += __shfl_down_sync(0xffffffffu, s, 1, 16);
        if ((t & 15) == 0) invb[t >> 4] = 1.0f / s;
    }
    __syncthreads();

    const int c0 = 2 * t;
    float csx = 0.f, csy = 0.f;
    #pragma unroll 4
    for (int row = 0; row < 16; row++){
        float inv = invb[row];
        float2 v = *reinterpret_cast<const float2*>(&buf[row][c0]);
        v.x *= inv; v.y *= inv;
        *reinterpret_cast<float2*>(ap + (size_t)row * NSK + c0) = v;
        csx += v.x; csy += v.y;
    }
    float* csp = g_cs + (size_t)(b * NHD + h) * NSK + c0;
    atomicAdd(csp + 0, csx);
    atomicAdd(csp + 1, csy);
}

// ---------------- t[b,h,j] += sum_{k in chunk} colsum[b,h,k] * v[b,k,j] ----------------
__global__ __launch_bounds__(256) void tred_kernel(const float* __restrict__ v){
    __shared__ float cs[NHD][64];
    int b = blockIdx.x, c = blockIdx.y, t = threadIdx.x;
    for (int i = t; i < NHD * 64; i += 256){
        int hh = i >> 6, kk = i & 63;
        cs[hh][kk] = g_cs[(size_t)(b * NHD + hh) * NSK + c * 64 + kk];
    }
    __syncthreads();
    float acc[NHD];
    #pragma unroll
    for (int hh = 0; hh < NHD; hh++) acc[hh] = 0.f;
    const float* vp = v + ((size_t)b * NSK + c * 64) * HDIM + t;
    #pragma unroll 4
    for (int k = 0; k < 64; k++){
        float vv = vp[(size_t)k * HDIM];
        #pragma unroll
        for (int hh = 0; hh < NHD; hh++) acc[hh] += cs[hh][k] * vv;
    }
    #pragma unroll
    for (int hh = 0; hh < NHD; hh++)
        atomicAdd(&g_t[(b * NHD + hh) * HDIM + t], acc[hh]);
}

// ---------------- xs = t @ W_V^T (per head), MLP + BN(eval) + mish + residual ----------------
__global__ __launch_bounds__(256) void final_kernel(
    const float* __restrict__ WV, const float* __restrict__ W1, const float* __restrict__ b1,
    const float* __restrict__ gamma, const float* __restrict__ beta,
    const float* __restrict__ rm, const float* __restrict__ rv, float* __restrict__ out)
{
    __shared__ float sxs[HDIM];
    int b = blockIdx.x, n = threadIdx.x;
    const float* tp = g_t + (b * NHD + (n >> 5)) * HDIM;
    const float* wv = WV + (size_t)n * HDIM;
    float s = 0.f;
    #pragma unroll 8
    for (int j = 0; j < HDIM; j++) s += tp[j] * wv[j];
    sxs[n] = s;
    __syncthreads();
    const float* w1 = W1 + (size_t)n * HDIM;
    float hsum = b1[n];
    #pragma unroll 8
    for (int j = 0; j < HDIM; j++) hsum += sxs[j] * w1[j];
    float hn = (hsum - rm[n]) * rsqrtf(rv[n] + 1e-5f) * gamma[n] + beta[n];
    float sp = log1pf(expf(hn));
    out[b * HDIM + n] = hn * tanhf(sp) + g_res[b * HDIM + n];
}

// ---------------- launch ----------------
extern "C" void kernel_launch(void* const* d_in, const int* in_sizes, int n_in,
                              void* d_out, int out_size)
{
    const float* q    = (const float*)d_in[0];
    const float* k    = (const float*)d_in[1];
    const float* v    = (const float*)d_in[2];
    const float* bias = (const float*)d_in[3];
    const float* WQ   = (const float*)d_in[4];
    const float* WK   = (const float*)d_in[5];
    const float* WV   = (const float*)d_in[6];
    const float* W1   = (const float*)d_in[7];
    const float* b1   = (const float*)d_in[8];
    const float* gm   = (const float*)d_in[9];
    const float* bt   = (const float*)d_in[10];
    const float* rm   = (const float*)d_in[11];
    const float* rv   = (const float*)d_in[12];

    float* out  = (float*)d_out;
    float* attn = out + NB * HDIM;   // (out, attention) in tuple order

    cudaFuncSetAttribute(attn_kernel, cudaFuncAttributeMaxDynamicSharedMemorySize, SMEM_ATTN);
    cudaFuncSetAttribute(proj_kernel, cudaFuncAttributeMaxDynamicSharedMemorySize, SMEM_PROJ);

    zero_kernel<<<512, 256>>>();
    proj_kernel<<<dim3(4, 128, 2), 256, SMEM_PROJ>>>(q, k, WQ, WK);
    res_kernel<<<dim3(NB, 16), 256>>>(q);
    attn_kernel<<<dim3(NB, NHD, 64), 512, SMEM_ATTN>>>(bias, attn);
    tred_kernel<<<dim3(NB, 16), 256>>>(v);
    final_kernel<<<NB, 256>>>(WV, W1, b1, gm, bt, rm, rv, out);
}